// round 4
// baseline (speedup 1.0000x reference)
#include <cuda_runtime.h>

// ---------------- problem constants ----------------
#define NN      2304      // N*N rows
#define KDIM    128       // hidden width / GEMM K
#define NCOLS   14400     // MODES*EY*EY
#define E0W     1060      // E0 side length
#define BMg     64        // GEMM row tile
#define BNg     96        // GEMM col tile (150 * 96 = 14400 exact)
#define EY_ELEMS (NN * NCOLS)   // 33177600
#define E0_ELEMS 1123600        // 1060*1060

// scratch (allocation-free rule: device globals). No vector accesses -> no
// alignment assumptions. g_zero is the universal null-input fallback; its
// capacity (2247200 floats) covers the largest footprint any role needs.
__device__ float  g_h[NN * KDIM];
__device__ float  g_eta[NN];
__device__ float  g_Ey[EY_ELEMS];
__device__ float  g_Tre[NN];
__device__ float  g_Tim[NN];
__device__ float  g_zero[2 * E0_ELEMS];

// ---------------------------------------------------------------------------
// Kernel 1: both MLPs up to the last layer. One block per row, 128 threads.
// ---------------------------------------------------------------------------
__global__ void __launch_bounds__(128) mlp_kernel(
    const float* hs,
    const float* nW0, const float* nb0,
    const float* nW1, const float* nb1,
    const float* nW2, const float* nb2,
    const float* eW0, const float* eb0,
    const float* eW1, const float* eb1)
{
    // null-input fallback (device-side, no host API needed)
    const float* HS  = hs  ? hs  : g_zero;
    const float* NW0 = nW0 ? nW0 : g_zero;  const float* NB0 = nb0 ? nb0 : g_zero;
    const float* NW1 = nW1 ? nW1 : g_zero;  const float* NB1 = nb1 ? nb1 : g_zero;
    const float* NW2 = nW2 ? nW2 : g_zero;  const float* NB2 = nb2 ? nb2 : g_zero;
    const float* EW0 = eW0 ? eW0 : g_zero;  const float* EB0 = eb0 ? eb0 : g_zero;
    const float* EW1 = eW1 ? eW1 : g_zero;  const float* EB1 = eb1 ? eb1 : g_zero;

    int p = blockIdx.x;
    int j = threadIdx.x;
    float x = HS[p];

    __shared__ float s1[KDIM];
    __shared__ float s2[KDIM];

    // ---- neff branch ----
    s1[j] = fmaxf(fmaf(x, NW0[j], NB0[j]), 0.0f);
    __syncthreads();
    float acc = NB1[j];
#pragma unroll 8
    for (int k = 0; k < KDIM; ++k)
        acc = fmaf(s1[k], NW1[k * KDIM + j], acc);
    float h2 = fmaxf(acc, 0.0f);
    __syncthreads();
    s2[j] = h2 * NW2[j];          // nW2 shape (128,1)
    __syncthreads();
    for (int off = 64; off > 0; off >>= 1) {
        if (j < off) s2[j] += s2[j + off];
        __syncthreads();
    }
    if (j == 0) {
        float neff = s2[0] + NB2[0];
        g_eta[p] = neff / (neff + 1.0f);   // N0 = 1
    }

    // ---- enn branch ----
    __syncthreads();
    s1[j] = fmaxf(fmaf(x, EW0[j], EB0[j]), 0.0f);
    __syncthreads();
    acc = EB1[j];
#pragma unroll 8
    for (int k = 0; k < KDIM; ++k)
        acc = fmaf(s1[k], EW1[k * KDIM + j], acc);
    g_h[p * KDIM + j] = fmaxf(acc, 0.0f);
}

// ---------------------------------------------------------------------------
// Kernel 2: g_Ey = g_h[2304x128] @ eW2[128x14400] + eb2.
// 64x96 tile / block, 256 threads (8 warps x 32 lanes).
// Warp w owns rows p0+8w..p0+8w+7; lane owns cols c0+lane, +32, +64.
// W tile in 48KB static smem (scalar, conflict-free); H via warp-uniform LDG.
// ---------------------------------------------------------------------------
__global__ void __launch_bounds__(256) gemm_kernel(
    const float* W,      // eW2, row-major [128][14400]
    const float* bias)   // eb2 [14400]
{
    const float* Wp = W    ? W    : g_zero;
    const float* Bp = bias ? bias : g_zero;

    __shared__ float Ws[KDIM * BNg];   // 128*96*4 = 49152 bytes

    const int c0 = blockIdx.x * BNg;
    const int p0 = blockIdx.y * BMg;
    const int t  = threadIdx.x;

    for (int i = t; i < KDIM * BNg; i += 256) {
        int k = i / BNg;
        int c = i - k * BNg;
        Ws[i] = Wp[k * NCOLS + c0 + c];
    }
    __syncthreads();

    const int w    = t >> 5;           // warp id: row group
    const int lane = t & 31;
    const int r0   = p0 + w * 8;

    float acc[8][3];
#pragma unroll
    for (int q = 0; q < 3; ++q) {
        float b = Bp[c0 + lane + 32 * q];
#pragma unroll
        for (int r = 0; r < 8; ++r) acc[r][q] = b;
    }

    const float* hbase = &g_h[r0 * KDIM];

#pragma unroll 4
    for (int k = 0; k < KDIM; ++k) {
        float w0 = Ws[k * BNg + lane];
        float w1 = Ws[k * BNg + lane + 32];
        float w2 = Ws[k * BNg + lane + 64];
        float h[8];
#pragma unroll
        for (int r = 0; r < 8; ++r) h[r] = hbase[r * KDIM + k]; // uniform LDG
#pragma unroll
        for (int r = 0; r < 8; ++r) {
            acc[r][0] = fmaf(h[r], w0, acc[r][0]);
            acc[r][1] = fmaf(h[r], w1, acc[r][1]);
            acc[r][2] = fmaf(h[r], w2, acc[r][2]);
        }
    }

#pragma unroll
    for (int r = 0; r < 8; ++r) {
        float* orow = &g_Ey[(r0 + r) * NCOLS + c0];
#pragma unroll
        for (int q = 0; q < 3; ++q)
            orow[lane + 32 * q] = acc[r][q];
    }
}

// ---------------------------------------------------------------------------
// Kernel 3: T[p] = 0.005 * eta[p] * sum_e Ey[p,e] * E0_slice[p,e]
// E0_slice[p, i*20+a, j*20+b] = E0[i*20 + f/960, j*20 + f%960], f=p*400+a*20+b
// One block per row p, 256 threads. stride=2 supports interleaved complex E0.
// ---------------------------------------------------------------------------
__global__ void __launch_bounds__(256) esum_kernel(
    const float* E0r_in, const float* E0i_in, int stride)
{
    const float* E0r = E0r_in ? E0r_in : g_zero;
    const float* E0i = E0i_in ? E0i_in : g_zero;

    const int p = blockIdx.x;
    const int t = threadIdx.x;
    float sre = 0.f, sim = 0.f;

    const int f0 = p * 400;
    for (int e = t; e < NCOLS; e += 256) {
        int y = e / 120;
        int x = e - y * 120;
        int i = y / 20, a = y - i * 20;
        int j = x / 20, b = x - j * 20;
        int f = f0 + a * 20 + b;
        int row = f / 960;
        int col = f - row * 960;
        int idx = (i * 20 + row) * E0W + (j * 20 + col);
        float g = g_Ey[p * NCOLS + e];
        sre = fmaf(g, E0r[idx * stride], sre);
        sim = fmaf(g, E0i[idx * stride], sim);
    }

#pragma unroll
    for (int off = 16; off > 0; off >>= 1) {
        sre += __shfl_down_sync(0xffffffffu, sre, off);
        sim += __shfl_down_sync(0xffffffffu, sim, off);
    }
    __shared__ float wr[8], wi[8];
    if ((t & 31) == 0) { wr[t >> 5] = sre; wi[t >> 5] = sim; }
    __syncthreads();
    if (t == 0) {
        float tre = 0.f, tim = 0.f;
        for (int q = 0; q < 8; ++q) { tre += wr[q]; tim += wi[q]; }
        float s = 0.005f * g_eta[p];   // 2*C_EPSILON*dx*dx = 2*(1/20)^2
        g_Tre[p] = s * tre;
        g_Tim[p] = s * tim;
    }
}

// ---------------------------------------------------------------------------
// Kernel 4: pack -> d_out. SCALAR FLOAT writes only, exactly `cnt` of them,
// cnt <= out_size in every mode. No unit assumption can overrun the buffer.
// mode 0: [Ey, T.real]            (out_size == EY+NN, f32)
// mode 1: [Ey, T re/im pairs]     (out_size == EY+2NN, f32)
// mode 2: [Ey]                    (out_size == EY)
// mode 3: [T re/im pairs]         (out_size == 4608)
// mode 4: [T.real]                (out_size == 2304)
// mode 5: [Ey, T pairs] capped    (unknown out_size; cnt = out_size/4)
// ---------------------------------------------------------------------------
__global__ void pack_kernel(float* out, long long cnt, int mode)
{
    long long i = (long long)blockIdx.x * 256 + threadIdx.x;
    if (i >= cnt) return;

    float v = 0.f;
    if (mode == 0) {
        v = (i < EY_ELEMS) ? g_Ey[i] : g_Tre[i - EY_ELEMS];
    } else if (mode == 1 || mode == 5) {
        if (i < EY_ELEMS) v = g_Ey[i];
        else {
            long long q = i - EY_ELEMS;
            if (q < 2 * NN) v = (q & 1) ? g_Tim[q >> 1] : g_Tre[q >> 1];
        }
    } else if (mode == 2) {
        v = g_Ey[i];
    } else if (mode == 3) {
        v = (i & 1) ? g_Tim[i >> 1] : g_Tre[i >> 1];
    } else { // mode 4
        v = g_Tre[i];
    }
    out[i] = v;
}

// ---------------------------------------------------------------------------
extern "C" void kernel_launch(void* const* d_in, const int* in_sizes, int n_in,
                              void* d_out, int out_size)
{
    // ---- input mapping: first-unused-exact-size, else nullptr (kernel
    //      substitutes g_zero). Pure host logic, no CUDA API calls. ----
    if (n_in > 64) n_in = 64;
    bool used[64];
    for (int i = 0; i < 64; ++i) used[i] = false;
    auto take = [&](int sz) -> const float* {
        for (int i = 0; i < n_in; ++i)
            if (!used[i] && in_sizes[i] == sz) {
                used[i] = true;
                return (const float*)d_in[i];
            }
        return nullptr;
    };

    const float* hs = take(2304);
    const float* E0r; const float* E0i; int e0stride;
    {
        const float* a = take(E0_ELEMS);
        if (a) { E0r = a; E0i = take(E0_ELEMS); e0stride = 1; }
        else {
            const float* c1 = take(2 * E0_ELEMS);
            const float* c2 = take(2 * E0_ELEMS);
            if (c1 && c2)      { E0r = c1;     E0i = c2;     e0stride = 2; }
            else if (c1)       { E0r = c1;     E0i = c1 + 1; e0stride = 2; }
            else               { E0r = nullptr; E0i = nullptr; e0stride = 1; }
        }
    }
    const float* nW0 = take(128);
    const float* nb0 = take(128);
    const float* nW1 = take(16384);
    const float* nb1 = take(128);
    const float* nW2 = take(128);
    const float* nb2 = take(1);
    const float* eW0 = take(128);
    const float* eb0 = take(128);
    const float* eW1 = take(16384);
    const float* eb1 = take(128);
    const float* eW2 = take(1843200);
    const float* eb2 = take(14400);
    float* out = (float*)d_out;

    // ---- output mode by out_size value; cnt never exceeds out_size ----
    long long cnt; int mode;
    if      (out_size == EY_ELEMS + NN)     { mode = 0; cnt = out_size; }
    else if (out_size == EY_ELEMS + 2 * NN) { mode = 1; cnt = out_size; }
    else if (out_size == EY_ELEMS)          { mode = 2; cnt = out_size; }
    else if (out_size == 2 * NN)            { mode = 3; cnt = out_size; }
    else if (out_size == NN)                { mode = 4; cnt = out_size; }
    else { mode = 5; cnt = out_size / 4; }   // unknown: conservative bytes-safe
    if (cnt < 1) cnt = 1;

    mlp_kernel<<<NN, 128>>>(hs, nW0, nb0, nW1, nb1, nW2, nb2,
                            eW0, eb0, eW1, eb1);

    dim3 g2(NCOLS / BNg, NN / BMg);          // 150 x 36
    gemm_kernel<<<g2, 256>>>(eW2, eb2);      // 48KB static smem, no attribute

    esum_kernel<<<NN, 256>>>(E0r, E0i, e0stride);

    pack_kernel<<<(unsigned)((cnt + 255) / 256), 256>>>(out, cnt, mode);
}

// round 6
// speedup vs baseline: 2.2227x; 2.2227x over previous
#include <cuda_runtime.h>
#include <cuda_bf16.h>
#include <cstdint>

// ---------------- problem constants ----------------
#define NN       2304
#define KDIM     128
#define KP       64              // packed bf16-pair count along K
#define NCOLS    14400
#define E0W      1060
#define EY_ELEMS (NN * NCOLS)    // 33177600
#define E0_ELEMS 1123600

// GEMM tiling
#define GM 128                   // rows per CTA
#define GN 64                    // cols per CTA
#define SPITCH 72                // smem row pitch (72%32==8 -> conflict-free)

// ---------------- scratch (device globals, allocation-free) ----------------
__device__ float    g_eta[NN];
__device__ uint32_t g_hhi[NN * KP];       // h split-hi, bf16 pairs
__device__ uint32_t g_hlo[NN * KP];       // h split-lo
__device__ uint32_t g_Whi[KP * NCOLS];    // W split-hi, packed along K
__device__ uint32_t g_Wlo[KP * NCOLS];
__device__ __align__(16) float g_Ey[EY_ELEMS];   // fallback output modes only
__device__ float    g_Tre[NN];
__device__ float    g_Tim[NN];
__device__ float    g_zero[2 * E0_ELEMS]; // universal null-input fallback

// ---------------------------------------------------------------------------
// helpers
// ---------------------------------------------------------------------------
__device__ __forceinline__ void bf16_split_pack(float x0, float x1,
                                                uint32_t& hi, uint32_t& lo)
{
    __nv_bfloat16 h0 = __float2bfloat16_rn(x0);
    __nv_bfloat16 h1 = __float2bfloat16_rn(x1);
    hi = (uint32_t)__bfloat16_as_ushort(h0)
       | ((uint32_t)__bfloat16_as_ushort(h1) << 16);
    __nv_bfloat16 l0 = __float2bfloat16_rn(x0 - __bfloat162float(h0));
    __nv_bfloat16 l1 = __float2bfloat16_rn(x1 - __bfloat162float(h1));
    lo = (uint32_t)__bfloat16_as_ushort(l0)
       | ((uint32_t)__bfloat16_as_ushort(l1) << 16);
}

// D += A(16x16 bf16) * B(16x8 bf16), fp32 accum. sm_80+ HMMA.
__device__ __forceinline__ void mma_bf16(float* c, const uint32_t* a,
                                         uint32_t b0, uint32_t b1)
{
    asm volatile(
        "mma.sync.aligned.m16n8k16.row.col.f32.bf16.bf16.f32 "
        "{%0,%1,%2,%3}, {%4,%5,%6,%7}, {%8,%9}, {%0,%1,%2,%3};\n"
        : "+f"(c[0]), "+f"(c[1]), "+f"(c[2]), "+f"(c[3])
        : "r"(a[0]), "r"(a[1]), "r"(a[2]), "r"(a[3]), "r"(b0), "r"(b1));
}

// ---------------------------------------------------------------------------
// Kernel 1: the two small MLPs; also emits split-bf16 packed h.
// One block per row p, 128 threads.
// ---------------------------------------------------------------------------
__global__ void __launch_bounds__(128) mlp_kernel(
    const float* hs,
    const float* nW0, const float* nb0, const float* nW1, const float* nb1,
    const float* nW2, const float* nb2,
    const float* eW0, const float* eb0, const float* eW1, const float* eb1)
{
    const float* HS  = hs  ? hs  : g_zero;
    const float* NW0 = nW0 ? nW0 : g_zero;  const float* NB0 = nb0 ? nb0 : g_zero;
    const float* NW1 = nW1 ? nW1 : g_zero;  const float* NB1 = nb1 ? nb1 : g_zero;
    const float* NW2 = nW2 ? nW2 : g_zero;  const float* NB2 = nb2 ? nb2 : g_zero;
    const float* EW0 = eW0 ? eW0 : g_zero;  const float* EB0 = eb0 ? eb0 : g_zero;
    const float* EW1 = eW1 ? eW1 : g_zero;  const float* EB1 = eb1 ? eb1 : g_zero;

    int p = blockIdx.x, j = threadIdx.x;
    float x = HS[p];
    __shared__ float s1[KDIM], s2[KDIM];

    // ---- neff branch ----
    s1[j] = fmaxf(fmaf(x, NW0[j], NB0[j]), 0.0f);
    __syncthreads();
    float acc = NB1[j];
#pragma unroll 8
    for (int k = 0; k < KDIM; ++k) acc = fmaf(s1[k], NW1[k * KDIM + j], acc);
    float h2 = fmaxf(acc, 0.0f);
    __syncthreads();
    s2[j] = h2 * NW2[j];
    __syncthreads();
    for (int off = 64; off > 0; off >>= 1) {
        if (j < off) s2[j] += s2[j + off];
        __syncthreads();
    }
    if (j == 0) {
        float neff = s2[0] + NB2[0];
        g_eta[p] = neff / (neff + 1.0f);   // N0 = 1
    }
    __syncthreads();

    // ---- enn branch ----
    s1[j] = fmaxf(fmaf(x, EW0[j], EB0[j]), 0.0f);
    __syncthreads();
    acc = EB1[j];
#pragma unroll 8
    for (int k = 0; k < KDIM; ++k) acc = fmaf(s1[k], EW1[k * KDIM + j], acc);
    float hval = fmaxf(acc, 0.0f);
    __syncthreads();
    s2[j] = hval;
    __syncthreads();
    if (j < KP) {
        uint32_t hi, lo;
        bf16_split_pack(s2[2 * j], s2[2 * j + 1], hi, lo);
        g_hhi[p * KP + j] = hi;
        g_hlo[p * KP + j] = lo;
    }
}

// ---------------------------------------------------------------------------
// Kernel 1b: split-pack eW2 into K-pair planes. id = kp*NCOLS + c.
// ---------------------------------------------------------------------------
__global__ void __launch_bounds__(256) wpack_kernel(const float* W_in)
{
    const float* W = W_in ? W_in : g_zero;
    int id = blockIdx.x * 256 + threadIdx.x;
    if (id >= KP * NCOLS) return;
    int kp = id / NCOLS, c = id - kp * NCOLS;
    float x0 = W[(2 * kp) * NCOLS + c];
    float x1 = W[(2 * kp + 1) * NCOLS + c];
    bf16_split_pack(x0, x1, g_Whi[id], g_Wlo[id]);
}

// ---------------------------------------------------------------------------
// Kernel 2: HMMA bf16 split GEMM. Ey = h @ W + bias, written to eyout
// (d_out in fast mode, g_Ey otherwise).
// CTA: 128 rows x 64 cols, 8 warps (one 16-row band each), full K in regs/smem.
// B tile (W) staged in smem pitch-72 (bank-conflict-free for the qk*8+qrow
// access pattern). A (h) fragments read from L2-resident packed arrays.
// ---------------------------------------------------------------------------
__global__ void __launch_bounds__(256) gemm_mma(
    const float* bias_in, float* eyout)
{
    const float* bias = bias_in ? bias_in : g_zero;
    float* o = eyout ? eyout : g_Ey;

    __shared__ uint32_t sBhi[KP * SPITCH];
    __shared__ uint32_t sBlo[KP * SPITCH];

    const int c0 = blockIdx.x * GN;
    const int p0 = blockIdx.y * GM;
    const int t = threadIdx.x;
    const int w = t >> 5, lane = t & 31;

    // stage B tile: kp 0..63 x col 0..63
    for (int i = t; i < KP * GN; i += 256) {
        int kp = i >> 6, c = i & 63;
        sBhi[kp * SPITCH + c] = g_Whi[kp * NCOLS + c0 + c];
        sBlo[kp * SPITCH + c] = g_Wlo[kp * NCOLS + c0 + c];
    }
    __syncthreads();

    const int r0   = p0 + w * 16;
    const int qrow = lane >> 2;   // 0..7
    const int qk   = lane & 3;    // 0..3

    float acc[8][4];
#pragma unroll
    for (int s = 0; s < 8; ++s)
#pragma unroll
        for (int q = 0; q < 4; ++q) acc[s][q] = 0.0f;

    const uint32_t* Ahi = g_hhi + (r0 + qrow) * KP + qk;
    const uint32_t* Alo = g_hlo + (r0 + qrow) * KP + qk;

    for (int ks = 0; ks < 8; ++ks) {
        const int kb = ks * 8;
        uint32_t ah[4], al[4];
        ah[0] = Ahi[kb];              ah[1] = Ahi[kb + 8 * KP];
        ah[2] = Ahi[kb + 4];          ah[3] = Ahi[kb + 8 * KP + 4];
        al[0] = Alo[kb];              al[1] = Alo[kb + 8 * KP];
        al[2] = Alo[kb + 4];          al[3] = Alo[kb + 8 * KP + 4];

        const uint32_t* rh0 = &sBhi[(kb + qk) * SPITCH + qrow];
        const uint32_t* rh1 = &sBhi[(kb + qk + 4) * SPITCH + qrow];
        const uint32_t* rl0 = &sBlo[(kb + qk) * SPITCH + qrow];
        const uint32_t* rl1 = &sBlo[(kb + qk + 4) * SPITCH + qrow];

#pragma unroll
        for (int s = 0; s < 8; ++s) {
            uint32_t bh0 = rh0[s * 8];
            uint32_t bh1 = rh1[s * 8];
            uint32_t bl0 = rl0[s * 8];
            uint32_t bl1 = rl1[s * 8];
            mma_bf16(acc[s], ah, bh0, bh1);
            mma_bf16(acc[s], ah, bl0, bl1);
            mma_bf16(acc[s], al, bh0, bh1);
        }
    }

    // epilogue: bias + direct coalesced float2 stores
#pragma unroll
    for (int s = 0; s < 8; ++s) {
        int c = c0 + s * 8 + qk * 2;
        float b0 = bias[c], b1 = bias[c + 1];
        size_t r = (size_t)(r0 + qrow);
        float2 v0 = make_float2(acc[s][0] + b0, acc[s][1] + b1);
        float2 v1 = make_float2(acc[s][2] + b0, acc[s][3] + b1);
        *(float2*)&o[r * NCOLS + c]       = v0;
        *(float2*)&o[(r + 8) * NCOLS + c] = v1;
    }
}

// ---------------------------------------------------------------------------
// Kernel 3: T[p] = 0.005 * eta[p] * sum_e Ey[p,e] * E0_slice[p,e]
// (proven in round 4). stride=2 supports interleaved complex E0.
// ---------------------------------------------------------------------------
__global__ void __launch_bounds__(256) esum_kernel(
    const float* ey_in, const float* E0r_in, const float* E0i_in,
    int stride, float* outT)
{
    const float* ey  = ey_in  ? ey_in  : g_Ey;
    const float* E0r = E0r_in ? E0r_in : g_zero;
    const float* E0i = E0i_in ? E0i_in : g_zero;

    const int p = blockIdx.x, t = threadIdx.x;
    float sre = 0.f, sim = 0.f;
    const int f0 = p * 400;
    for (int e = t; e < NCOLS; e += 256) {
        int y = e / 120, x = e - y * 120;
        int i = y / 20, a = y - i * 20;
        int j = x / 20, b = x - j * 20;
        int f = f0 + a * 20 + b;
        int row = f / 960, col = f - row * 960;
        int idx = (i * 20 + row) * E0W + (j * 20 + col);
        float g = ey[(size_t)p * NCOLS + e];
        sre = fmaf(g, E0r[idx * stride], sre);
        sim = fmaf(g, E0i[idx * stride], sim);
    }
#pragma unroll
    for (int off = 16; off > 0; off >>= 1) {
        sre += __shfl_down_sync(0xffffffffu, sre, off);
        sim += __shfl_down_sync(0xffffffffu, sim, off);
    }
    __shared__ float wr[8], wi[8];
    if ((t & 31) == 0) { wr[t >> 5] = sre; wi[t >> 5] = sim; }
    __syncthreads();
    if (t == 0) {
        float tre = 0.f, tim = 0.f;
        for (int q = 0; q < 8; ++q) { tre += wr[q]; tim += wi[q]; }
        float s = 0.005f * g_eta[p];   // 2*C_EPSILON*dx*dx
        g_Tre[p] = s * tre;
        g_Tim[p] = s * tim;
        if (outT) outT[p] = s * tre;
    }
}

// ---------------------------------------------------------------------------
// Kernel 4 (fallback modes only): scalar-float pack, never exceeds cnt.
// ---------------------------------------------------------------------------
__global__ void pack_kernel(float* out, long long cnt, int mode)
{
    long long i = (long long)blockIdx.x * 256 + threadIdx.x;
    if (i >= cnt) return;
    float v = 0.f;
    if (mode == 1 || mode == 5) {
        if (i < EY_ELEMS) v = g_Ey[i];
        else {
            long long q = i - EY_ELEMS;
            if (q < 2 * NN) v = (q & 1) ? g_Tim[q >> 1] : g_Tre[q >> 1];
        }
    } else if (mode == 2) v = g_Ey[i];
    else if (mode == 3) v = (i & 1) ? g_Tim[i >> 1] : g_Tre[i >> 1];
    else if (mode == 4) v = g_Tre[i];
    out[i] = v;
}

// ---------------------------------------------------------------------------
extern "C" void kernel_launch(void* const* d_in, const int* in_sizes, int n_in,
                              void* d_out, int out_size)
{
    if (n_in > 64) n_in = 64;
    bool used[64];
    for (int i = 0; i < 64; ++i) used[i] = false;
    auto take = [&](int sz) -> const float* {
        for (int i = 0; i < n_in; ++i)
            if (!used[i] && in_sizes[i] == sz) {
                used[i] = true;
                return (const float*)d_in[i];
            }
        return nullptr;
    };

    const float* hs = take(2304);
    const float* E0r; const float* E0i; int e0stride;
    {
        const float* a = take(E0_ELEMS);
        if (a) { E0r = a; E0i = take(E0_ELEMS); e0stride = 1; }
        else {
            const float* c1 = take(2 * E0_ELEMS);
            const float* c2 = take(2 * E0_ELEMS);
            if (c1 && c2)      { E0r = c1; E0i = c2;     e0stride = 2; }
            else if (c1)       { E0r = c1; E0i = c1 + 1; e0stride = 2; }
            else               { E0r = nullptr; E0i = nullptr; e0stride = 1; }
        }
    }
    const float* nW0 = take(128);
    const float* nb0 = take(128);
    const float* nW1 = take(16384);
    const float* nb1 = take(128);
    const float* nW2 = take(128);
    const float* nb2 = take(1);
    const float* eW0 = take(128);
    const float* eb0 = take(128);
    const float* eW1 = take(16384);
    const float* eb1 = take(128);
    const float* eW2 = take(1843200);
    const float* eb2 = take(14400);
    float* out = (float*)d_out;

    const bool fast = (out_size == EY_ELEMS + NN);   // confirmed in round 4

    mlp_kernel<<<NN, 128>>>(hs, nW0, nb0, nW1, nb1, nW2, nb2,
                            eW0, eb0, eW1, eb1);
    wpack_kernel<<<(KP * NCOLS + 255) / 256, 256>>>(eW2);

    gemm_mma<<<dim3(NCOLS / GN, NN / GM), 256>>>(eb2, fast ? out : nullptr);

    esum_kernel<<<NN, 256>>>(fast ? out : nullptr, E0r, E0i, e0stride,
                             fast ? out + EY_ELEMS : nullptr);

    if (!fast) {
        long long cnt; int mode;
        if      (out_size == EY_ELEMS + 2 * NN) { mode = 1; cnt = out_size; }
        else if (out_size == EY_ELEMS)          { mode = 2; cnt = out_size; }
        else if (out_size == 2 * NN)            { mode = 3; cnt = out_size; }
        else if (out_size == NN)                { mode = 4; cnt = out_size; }
        else { mode = 5; cnt = out_size / 4; }
        if (cnt < 1) cnt = 1;
        pack_kernel<<<(unsigned)((cnt + 255) / 256), 256>>>(out, cnt, mode);
    }
}

// round 7
// speedup vs baseline: 2.5451x; 1.1450x over previous
#include <cuda_runtime.h>
#include <cuda_bf16.h>
#include <cstdint>

// ---------------- problem constants ----------------
#define NN       2304
#define KDIM     128
#define KP       64              // packed bf16-pair count along K
#define NCOLS    14400
#define E0W      1060
#define EY_ELEMS (NN * NCOLS)    // 33177600
#define E0_ELEMS 1123600

// GEMM tiling
#define GM 256                   // rows per CTA (2 row-tiles of 16 per warp)
#define GN 64                    // cols per CTA
#define SPITCH 72                // smem row pitch (72%32==8 -> conflict-free)

// ---------------- scratch (device globals, allocation-free) ----------------
__device__ float    g_eta[NN];
__device__ uint32_t g_hhi[NN * KP];       // h split-hi, bf16 pairs
__device__ uint32_t g_hlo[NN * KP];       // h split-lo
__device__ uint32_t g_Whi[KP * NCOLS];    // W split-hi, packed along K
__device__ uint32_t g_Wlo[KP * NCOLS];
__device__ int      g_tbl[NCOLS];         // packed (tij<<9 | ab) gather table
__device__ __align__(16) float g_Ey[EY_ELEMS];   // fallback output modes only
__device__ float    g_Tre[NN];
__device__ float    g_Tim[NN];
__device__ float    g_zero[2 * E0_ELEMS]; // universal null-input fallback

// ---------------------------------------------------------------------------
// helpers
// ---------------------------------------------------------------------------
__device__ __forceinline__ void bf16_split_pack(float x0, float x1,
                                                uint32_t& hi, uint32_t& lo)
{
    __nv_bfloat16 h0 = __float2bfloat16_rn(x0);
    __nv_bfloat16 h1 = __float2bfloat16_rn(x1);
    hi = (uint32_t)__bfloat16_as_ushort(h0)
       | ((uint32_t)__bfloat16_as_ushort(h1) << 16);
    __nv_bfloat16 l0 = __float2bfloat16_rn(x0 - __bfloat162float(h0));
    __nv_bfloat16 l1 = __float2bfloat16_rn(x1 - __bfloat162float(h1));
    lo = (uint32_t)__bfloat16_as_ushort(l0)
       | ((uint32_t)__bfloat16_as_ushort(l1) << 16);
}

// D += A(16x16 bf16) * B(16x8 bf16), fp32 accum. sm_80+ HMMA.
__device__ __forceinline__ void mma_bf16(float* c, const uint32_t* a,
                                         uint32_t b0, uint32_t b1)
{
    asm volatile(
        "mma.sync.aligned.m16n8k16.row.col.f32.bf16.bf16.f32 "
        "{%0,%1,%2,%3}, {%4,%5,%6,%7}, {%8,%9}, {%0,%1,%2,%3};\n"
        : "+f"(c[0]), "+f"(c[1]), "+f"(c[2]), "+f"(c[3])
        : "r"(a[0]), "r"(a[1]), "r"(a[2]), "r"(a[3]), "r"(b0), "r"(b1));
}

// ---------------------------------------------------------------------------
// Kernel 0: build the p-independent gather table for esum.
// tbl[e] = ((i*20)*E0W + j*20) << 9 | (a*20 + b), with y=e/120, x=e%120,
// i=y/20, a=y%20, j=x/20, b=x%20.
// ---------------------------------------------------------------------------
__global__ void prep_kernel()
{
    int e = blockIdx.x * 256 + threadIdx.x;
    if (e >= NCOLS) return;
    int y = e / 120, x = e - y * 120;
    int i = y / 20, a = y - i * 20;
    int j = x / 20, b = x - j * 20;
    int tij = (i * 20) * E0W + j * 20;
    g_tbl[e] = (tij << 9) | (a * 20 + b);
}

// ---------------------------------------------------------------------------
// Kernel 1: the two small MLPs; also emits split-bf16 packed h.
// One block per row p, 128 threads.
// ---------------------------------------------------------------------------
__global__ void __launch_bounds__(128) mlp_kernel(
    const float* hs,
    const float* nW0, const float* nb0, const float* nW1, const float* nb1,
    const float* nW2, const float* nb2,
    const float* eW0, const float* eb0, const float* eW1, const float* eb1)
{
    const float* HS  = hs  ? hs  : g_zero;
    const float* NW0 = nW0 ? nW0 : g_zero;  const float* NB0 = nb0 ? nb0 : g_zero;
    const float* NW1 = nW1 ? nW1 : g_zero;  const float* NB1 = nb1 ? nb1 : g_zero;
    const float* NW2 = nW2 ? nW2 : g_zero;  const float* NB2 = nb2 ? nb2 : g_zero;
    const float* EW0 = eW0 ? eW0 : g_zero;  const float* EB0 = eb0 ? eb0 : g_zero;
    const float* EW1 = eW1 ? eW1 : g_zero;  const float* EB1 = eb1 ? eb1 : g_zero;

    int p = blockIdx.x, j = threadIdx.x;
    float x = HS[p];
    __shared__ float s1[KDIM], s2[KDIM];

    // ---- neff branch ----
    s1[j] = fmaxf(fmaf(x, NW0[j], NB0[j]), 0.0f);
    __syncthreads();
    float acc = NB1[j];
#pragma unroll 8
    for (int k = 0; k < KDIM; ++k) acc = fmaf(s1[k], NW1[k * KDIM + j], acc);
    float h2 = fmaxf(acc, 0.0f);
    __syncthreads();
    s2[j] = h2 * NW2[j];
    __syncthreads();
    for (int off = 64; off > 0; off >>= 1) {
        if (j < off) s2[j] += s2[j + off];
        __syncthreads();
    }
    if (j == 0) {
        float neff = s2[0] + NB2[0];
        g_eta[p] = neff / (neff + 1.0f);   // N0 = 1
    }
    __syncthreads();

    // ---- enn branch ----
    s1[j] = fmaxf(fmaf(x, EW0[j], EB0[j]), 0.0f);
    __syncthreads();
    acc = EB1[j];
#pragma unroll 8
    for (int k = 0; k < KDIM; ++k) acc = fmaf(s1[k], EW1[k * KDIM + j], acc);
    float hval = fmaxf(acc, 0.0f);
    __syncthreads();
    s2[j] = hval;
    __syncthreads();
    if (j < KP) {
        uint32_t hi, lo;
        bf16_split_pack(s2[2 * j], s2[2 * j + 1], hi, lo);
        g_hhi[p * KP + j] = hi;
        g_hlo[p * KP + j] = lo;
    }
}

// ---------------------------------------------------------------------------
// Kernel 1b: split-pack eW2 into K-pair planes. id = kp*NCOLS + c.
// ---------------------------------------------------------------------------
__global__ void __launch_bounds__(256) wpack_kernel(const float* W_in)
{
    const float* W = W_in ? W_in : g_zero;
    int id = blockIdx.x * 256 + threadIdx.x;
    if (id >= KP * NCOLS) return;
    int kp = id / NCOLS, c = id - kp * NCOLS;
    float x0 = W[(2 * kp) * NCOLS + c];
    float x1 = W[(2 * kp + 1) * NCOLS + c];
    bf16_split_pack(x0, x1, g_Whi[id], g_Wlo[id]);
}

// ---------------------------------------------------------------------------
// Kernel 2: HMMA bf16 split GEMM. Ey = h @ W + bias -> eyout.
// CTA: 256 rows x 64 cols; 8 warps, each owning 32 rows = TWO 16-row MMA
// tiles sharing the same B fragments (4 LDS feed 6 MMAs).
// B tile staged hi/lo in smem, pitch-72 (conflict-free, proven round 6).
// Fragment indexing identical to the round-6 validated layout.
// ---------------------------------------------------------------------------
__global__ void __launch_bounds__(256) gemm_mma(
    const float* bias_in, float* eyout)
{
    const float* bias = bias_in ? bias_in : g_zero;
    float* o = eyout ? eyout : g_Ey;

    __shared__ uint32_t sBhi[KP * SPITCH];
    __shared__ uint32_t sBlo[KP * SPITCH];

    const int c0 = blockIdx.x * GN;
    const int p0 = blockIdx.y * GM;
    const int t = threadIdx.x;
    const int w = t >> 5, lane = t & 31;

    // stage B tile: kp 0..63 x col 0..63
    for (int i = t; i < KP * GN; i += 256) {
        int kp = i >> 6, c = i & 63;
        sBhi[kp * SPITCH + c] = g_Whi[kp * NCOLS + c0 + c];
        sBlo[kp * SPITCH + c] = g_Wlo[kp * NCOLS + c0 + c];
    }
    __syncthreads();

    const int r0   = p0 + w * 32;
    const int qrow = lane >> 2;   // 0..7
    const int qk   = lane & 3;    // 0..3

    float acc[2][8][4];
#pragma unroll
    for (int u = 0; u < 2; ++u)
#pragma unroll
        for (int s = 0; s < 8; ++s)
#pragma unroll
            for (int q = 0; q < 4; ++q) acc[u][s][q] = 0.0f;

    const uint32_t* Ahi0 = g_hhi + (r0 + qrow) * KP + qk;
    const uint32_t* Alo0 = g_hlo + (r0 + qrow) * KP + qk;
    const uint32_t* Ahi1 = g_hhi + (r0 + 16 + qrow) * KP + qk;
    const uint32_t* Alo1 = g_hlo + (r0 + 16 + qrow) * KP + qk;

    for (int ks = 0; ks < 8; ++ks) {
        const int kb = ks * 8;
        uint32_t ah0[4], al0[4], ah1[4], al1[4];
        ah0[0] = Ahi0[kb];          ah0[1] = Ahi0[kb + 8 * KP];
        ah0[2] = Ahi0[kb + 4];      ah0[3] = Ahi0[kb + 8 * KP + 4];
        al0[0] = Alo0[kb];          al0[1] = Alo0[kb + 8 * KP];
        al0[2] = Alo0[kb + 4];      al0[3] = Alo0[kb + 8 * KP + 4];
        ah1[0] = Ahi1[kb];          ah1[1] = Ahi1[kb + 8 * KP];
        ah1[2] = Ahi1[kb + 4];      ah1[3] = Ahi1[kb + 8 * KP + 4];
        al1[0] = Alo1[kb];          al1[1] = Alo1[kb + 8 * KP];
        al1[2] = Alo1[kb + 4];      al1[3] = Alo1[kb + 8 * KP + 4];

        const uint32_t* rh0 = &sBhi[(kb + qk) * SPITCH + qrow];
        const uint32_t* rh1 = &sBhi[(kb + qk + 4) * SPITCH + qrow];
        const uint32_t* rl0 = &sBlo[(kb + qk) * SPITCH + qrow];
        const uint32_t* rl1 = &sBlo[(kb + qk + 4) * SPITCH + qrow];

#pragma unroll
        for (int s = 0; s < 8; ++s) {
            uint32_t bh0 = rh0[s * 8];
            uint32_t bh1 = rh1[s * 8];
            uint32_t bl0 = rl0[s * 8];
            uint32_t bl1 = rl1[s * 8];
            mma_bf16(acc[0][s], ah0, bh0, bh1);
            mma_bf16(acc[0][s], ah0, bl0, bl1);
            mma_bf16(acc[0][s], al0, bh0, bh1);
            mma_bf16(acc[1][s], ah1, bh0, bh1);
            mma_bf16(acc[1][s], ah1, bl0, bl1);
            mma_bf16(acc[1][s], al1, bh0, bh1);
        }
    }

    // epilogue: bias + direct coalesced float2 stores (two row tiles)
#pragma unroll
    for (int s = 0; s < 8; ++s) {
        int c = c0 + s * 8 + qk * 2;
        float b0 = bias[c], b1 = bias[c + 1];
#pragma unroll
        for (int u = 0; u < 2; ++u) {
            size_t r = (size_t)(r0 + 16 * u + qrow);
            float2 v0 = make_float2(acc[u][s][0] + b0, acc[u][s][1] + b1);
            float2 v1 = make_float2(acc[u][s][2] + b0, acc[u][s][3] + b1);
            *(float2*)&o[r * NCOLS + c]       = v0;
            *(float2*)&o[(r + 8) * NCOLS + c] = v1;
        }
    }
}

// ---------------------------------------------------------------------------
// Kernel 3: T[p] = 0.005 * eta[p] * sum_e Ey[p,e] * E0_slice[p,e]
// Table-driven gather: idx = base_p + (tbl>>9) + (tbl&511) + 100*wrap,
// wrap = (c0p + ab >= 960). No divisions in the inner loop.
// ---------------------------------------------------------------------------
__global__ void __launch_bounds__(256) esum_kernel(
    const float* ey_in, const float* E0r_in, const float* E0i_in,
    int stride, float* outT)
{
    const float* ey  = ey_in  ? ey_in  : g_Ey;
    const float* E0r = E0r_in ? E0r_in : g_zero;
    const float* E0i = E0i_in ? E0i_in : g_zero;

    const int p = blockIdx.x, t = threadIdx.x;
    const int f0  = p * 400;
    const int r0p = f0 / 960;
    const int c0p = f0 - r0p * 960;
    const int base = r0p * E0W + c0p;
    const int lim  = 960 - c0p;        // wrap when ab >= lim

    float sre = 0.f, sim = 0.f;
    const float* eyrow = ey + (size_t)p * NCOLS;

#pragma unroll 4
    for (int e = t; e < NCOLS; e += 256) {
        int tb  = g_tbl[e];
        int ab  = tb & 511;
        int idx = base + (tb >> 9) + ab + ((ab >= lim) ? 100 : 0);
        float g = eyrow[e];
        sre = fmaf(g, E0r[idx * stride], sre);
        sim = fmaf(g, E0i[idx * stride], sim);
    }

#pragma unroll
    for (int off = 16; off > 0; off >>= 1) {
        sre += __shfl_down_sync(0xffffffffu, sre, off);
        sim += __shfl_down_sync(0xffffffffu, sim, off);
    }
    __shared__ float wr[8], wi[8];
    if ((t & 31) == 0) { wr[t >> 5] = sre; wi[t >> 5] = sim; }
    __syncthreads();
    if (t == 0) {
        float tre = 0.f, tim = 0.f;
        for (int q = 0; q < 8; ++q) { tre += wr[q]; tim += wi[q]; }
        float s = 0.005f * g_eta[p];   // 2*C_EPSILON*dx*dx
        g_Tre[p] = s * tre;
        g_Tim[p] = s * tim;
        if (outT) outT[p] = s * tre;
    }
}

// ---------------------------------------------------------------------------
// Kernel 4 (fallback modes only): scalar-float pack, never exceeds cnt.
// ---------------------------------------------------------------------------
__global__ void pack_kernel(float* out, long long cnt, int mode)
{
    long long i = (long long)blockIdx.x * 256 + threadIdx.x;
    if (i >= cnt) return;
    float v = 0.f;
    if (mode == 1 || mode == 5) {
        if (i < EY_ELEMS) v = g_Ey[i];
        else {
            long long q = i - EY_ELEMS;
            if (q < 2 * NN) v = (q & 1) ? g_Tim[q >> 1] : g_Tre[q >> 1];
        }
    } else if (mode == 2) v = g_Ey[i];
    else if (mode == 3) v = (i & 1) ? g_Tim[i >> 1] : g_Tre[i >> 1];
    else if (mode == 4) v = g_Tre[i];
    out[i] = v;
}

// ---------------------------------------------------------------------------
extern "C" void kernel_launch(void* const* d_in, const int* in_sizes, int n_in,
                              void* d_out, int out_size)
{
    if (n_in > 64) n_in = 64;
    bool used[64];
    for (int i = 0; i < 64; ++i) used[i] = false;
    auto take = [&](int sz) -> const float* {
        for (int i = 0; i < n_in; ++i)
            if (!used[i] && in_sizes[i] == sz) {
                used[i] = true;
                return (const float*)d_in[i];
            }
        return nullptr;
    };

    const float* hs = take(2304);
    const float* E0r; const float* E0i; int e0stride;
    {
        const float* a = take(E0_ELEMS);
        if (a) { E0r = a; E0i = take(E0_ELEMS); e0stride = 1; }
        else {
            const float* c1 = take(2 * E0_ELEMS);
            const float* c2 = take(2 * E0_ELEMS);
            if (c1 && c2)      { E0r = c1; E0i = c2;     e0stride = 2; }
            else if (c1)       { E0r = c1; E0i = c1 + 1; e0stride = 2; }
            else               { E0r = nullptr; E0i = nullptr; e0stride = 1; }
        }
    }
    const float* nW0 = take(128);
    const float* nb0 = take(128);
    const float* nW1 = take(16384);
    const float* nb1 = take(128);
    const float* nW2 = take(128);
    const float* nb2 = take(1);
    const float* eW0 = take(128);
    const float* eb0 = take(128);
    const float* eW1 = take(16384);
    const float* eb1 = take(128);
    const float* eW2 = take(1843200);
    const float* eb2 = take(14400);
    float* out = (float*)d_out;

    const bool fast = (out_size == EY_ELEMS + NN);   // confirmed in round 4

    prep_kernel<<<(NCOLS + 255) / 256, 256>>>();
    mlp_kernel<<<NN, 128>>>(hs, nW0, nb0, nW1, nb1, nW2, nb2,
                            eW0, eb0, eW1, eb1);
    wpack_kernel<<<(KP * NCOLS + 255) / 256, 256>>>(eW2);

    gemm_mma<<<dim3(NCOLS / GN, NN / GM), 256>>>(eb2, fast ? out : nullptr);

    esum_kernel<<<NN, 256>>>(fast ? out : nullptr, E0r, E0i, e0stride,
                             fast ? out + EY_ELEMS : nullptr);

    if (!fast) {
        long long cnt; int mode;
        if      (out_size == EY_ELEMS + 2 * NN) { mode = 1; cnt = out_size; }
        else if (out_size == EY_ELEMS)          { mode = 2; cnt = out_size; }
        else if (out_size == 2 * NN)            { mode = 3; cnt = out_size; }
        else if (out_size == NN)                { mode = 4; cnt = out_size; }
        else { mode = 5; cnt = out_size / 4; }
        if (cnt < 1) cnt = 1;
        pack_kernel<<<(unsigned)((cnt + 255) / 256), 256>>>(out, cnt, mode);
    }
}

// round 8
// speedup vs baseline: 3.2358x; 1.2714x over previous
#include <cuda_runtime.h>
#include <cuda_bf16.h>
#include <cstdint>

// ---------------- problem constants ----------------
#define NN       2304
#define KDIM     128
#define KP       64              // packed bf16-pair count along K
#define NCOLS    14400
#define E0W      1060
#define EY_ELEMS (NN * NCOLS)    // 33177600
#define E0_ELEMS 1123600

// GEMM tiling
#define GM 256                   // rows per CTA (2 row-tiles of 16 per warp)
#define GN 64                    // cols per CTA
#define SPITCH 72                // smem row pitch (72%32==8 -> conflict-free)
#define NMG (NN / 16)            // 144 16-row fragment groups
#define FRAG_N (NMG * 8 * 32)    // uint4 fragments per plane = 36864

// ---------------- scratch (device globals, allocation-free) ----------------
__device__ float    g_eta[NN];
__device__ uint32_t g_hhi[NN * KP];       // h split-hi, bf16 pairs
__device__ uint32_t g_hlo[NN * KP];       // h split-lo
__device__ __align__(16) uint4 g_fragHi[FRAG_N];  // A fragments, coalesced
__device__ __align__(16) uint4 g_fragLo[FRAG_N];
__device__ uint32_t g_Whi[KP * NCOLS];    // W split-hi, packed along K
__device__ uint32_t g_Wlo[KP * NCOLS];
__device__ int      g_tbl[NCOLS];         // packed (tij<<9 | ab) gather table
__device__ __align__(16) float g_Ey[EY_ELEMS];   // fallback output modes only
__device__ float    g_Tre[NN];
__device__ float    g_Tim[NN];
__device__ float    g_zero[2 * E0_ELEMS]; // universal null-input fallback

// ---------------------------------------------------------------------------
// helpers
// ---------------------------------------------------------------------------
__device__ __forceinline__ void bf16_split_pack(float x0, float x1,
                                                uint32_t& hi, uint32_t& lo)
{
    __nv_bfloat16 h0 = __float2bfloat16_rn(x0);
    __nv_bfloat16 h1 = __float2bfloat16_rn(x1);
    hi = (uint32_t)__bfloat16_as_ushort(h0)
       | ((uint32_t)__bfloat16_as_ushort(h1) << 16);
    __nv_bfloat16 l0 = __float2bfloat16_rn(x0 - __bfloat162float(h0));
    __nv_bfloat16 l1 = __float2bfloat16_rn(x1 - __bfloat162float(h1));
    lo = (uint32_t)__bfloat16_as_ushort(l0)
       | ((uint32_t)__bfloat16_as_ushort(l1) << 16);
}

// D += A(16x16 bf16) * B(16x8 bf16), fp32 accum. sm_80+ HMMA.
__device__ __forceinline__ void mma_bf16(float* c, const uint4& a,
                                         uint32_t b0, uint32_t b1)
{
    asm volatile(
        "mma.sync.aligned.m16n8k16.row.col.f32.bf16.bf16.f32 "
        "{%0,%1,%2,%3}, {%4,%5,%6,%7}, {%8,%9}, {%0,%1,%2,%3};\n"
        : "+f"(c[0]), "+f"(c[1]), "+f"(c[2]), "+f"(c[3])
        : "r"(a.x), "r"(a.y), "r"(a.z), "r"(a.w), "r"(b0), "r"(b1));
}

// ---------------------------------------------------------------------------
// Kernel 0: build the p-independent gather table for esum.
// ---------------------------------------------------------------------------
__global__ void prep_kernel()
{
    int e = blockIdx.x * 256 + threadIdx.x;
    if (e >= NCOLS) return;
    int y = e / 120, x = e - y * 120;
    int i = y / 20, a = y - i * 20;
    int j = x / 20, b = x - j * 20;
    int tij = (i * 20) * E0W + j * 20;
    g_tbl[e] = (tij << 9) | (a * 20 + b);
}

// ---------------------------------------------------------------------------
// Kernel 1: the two small MLPs; also emits split-bf16 packed h.
// ---------------------------------------------------------------------------
__global__ void __launch_bounds__(128) mlp_kernel(
    const float* hs,
    const float* nW0, const float* nb0, const float* nW1, const float* nb1,
    const float* nW2, const float* nb2,
    const float* eW0, const float* eb0, const float* eW1, const float* eb1)
{
    const float* HS  = hs  ? hs  : g_zero;
    const float* NW0 = nW0 ? nW0 : g_zero;  const float* NB0 = nb0 ? nb0 : g_zero;
    const float* NW1 = nW1 ? nW1 : g_zero;  const float* NB1 = nb1 ? nb1 : g_zero;
    const float* NW2 = nW2 ? nW2 : g_zero;  const float* NB2 = nb2 ? nb2 : g_zero;
    const float* EW0 = eW0 ? eW0 : g_zero;  const float* EB0 = eb0 ? eb0 : g_zero;
    const float* EW1 = eW1 ? eW1 : g_zero;  const float* EB1 = eb1 ? eb1 : g_zero;

    int p = blockIdx.x, j = threadIdx.x;
    float x = HS[p];
    __shared__ float s1[KDIM], s2[KDIM];

    // ---- neff branch ----
    s1[j] = fmaxf(fmaf(x, NW0[j], NB0[j]), 0.0f);
    __syncthreads();
    float acc = NB1[j];
#pragma unroll 8
    for (int k = 0; k < KDIM; ++k) acc = fmaf(s1[k], NW1[k * KDIM + j], acc);
    float h2 = fmaxf(acc, 0.0f);
    __syncthreads();
    s2[j] = h2 * NW2[j];
    __syncthreads();
    for (int off = 64; off > 0; off >>= 1) {
        if (j < off) s2[j] += s2[j + off];
        __syncthreads();
    }
    if (j == 0) {
        float neff = s2[0] + NB2[0];
        g_eta[p] = neff / (neff + 1.0f);   // N0 = 1
    }
    __syncthreads();

    // ---- enn branch ----
    s1[j] = fmaxf(fmaf(x, EW0[j], EB0[j]), 0.0f);
    __syncthreads();
    acc = EB1[j];
#pragma unroll 8
    for (int k = 0; k < KDIM; ++k) acc = fmaf(s1[k], EW1[k * KDIM + j], acc);
    float hval = fmaxf(acc, 0.0f);
    __syncthreads();
    s2[j] = hval;
    __syncthreads();
    if (j < KP) {
        uint32_t hi, lo;
        bf16_split_pack(s2[2 * j], s2[2 * j + 1], hi, lo);
        g_hhi[p * KP + j] = hi;
        g_hlo[p * KP + j] = lo;
    }
}

// ---------------------------------------------------------------------------
// Kernel 1b: split-pack eW2 into K-pair planes.
// ---------------------------------------------------------------------------
__global__ void __launch_bounds__(256) wpack_kernel(const float* W_in)
{
    const float* W = W_in ? W_in : g_zero;
    int id = blockIdx.x * 256 + threadIdx.x;
    if (id >= KP * NCOLS) return;
    int kp = id / NCOLS, c = id - kp * NCOLS;
    float x0 = W[(2 * kp) * NCOLS + c];
    float x1 = W[(2 * kp + 1) * NCOLS + c];
    bf16_split_pack(x0, x1, g_Whi[id], g_Wlo[id]);
}

// ---------------------------------------------------------------------------
// Kernel 1c: swizzle h into A-fragment order. One uint4 per thread = the
// exact 4-register m16k16 fragment for (16-row group mg, k-step ks, lane):
//   q0=(qrow, kb+qk)  q1=(qrow+8, kb+qk)  q2=(qrow, kb+qk+4)  q3=(qrow+8, +4)
// Values bit-identical to the round-6/7 validated LDG pattern.
// ---------------------------------------------------------------------------
__global__ void __launch_bounds__(256) hfrag_kernel()
{
    int id = blockIdx.x * 256 + threadIdx.x;
    if (id >= 2 * FRAG_N) return;
    int plane = id / FRAG_N;
    int r = id - plane * FRAG_N;
    int lane = r & 31;
    int ks = (r >> 5) & 7;
    int mg = r >> 8;
    int qrow = lane >> 2, qk = lane & 3;
    int row = mg * 16 + qrow;
    int kp  = ks * 8 + qk;
    const uint32_t* src = plane ? g_hlo : g_hhi;
    uint4 v;
    v.x = src[row * KP + kp];
    v.y = src[(row + 8) * KP + kp];
    v.z = src[row * KP + kp + 4];
    v.w = src[(row + 8) * KP + kp + 4];
    (plane ? g_fragLo : g_fragHi)[r] = v;
}

// ---------------------------------------------------------------------------
// Kernel 2: HMMA bf16 split GEMM. Ey = h @ W + bias -> eyout.
// CTA: 256 rows x 64 cols; 8 warps x TWO 16-row tiles sharing B fragments.
// A fragments: one coalesced LDG.128 each from g_fragHi/Lo.
// B tile: hi/lo smem, pitch-72 conflict-free (proven round 6/7).
// ---------------------------------------------------------------------------
__global__ void __launch_bounds__(256) gemm_mma(
    const float* bias_in, float* eyout)
{
    const float* bias = bias_in ? bias_in : g_zero;
    float* o = eyout ? eyout : g_Ey;

    __shared__ uint32_t sBhi[KP * SPITCH];
    __shared__ uint32_t sBlo[KP * SPITCH];

    const int c0 = blockIdx.x * GN;
    const int p0 = blockIdx.y * GM;
    const int t = threadIdx.x;
    const int w = t >> 5, lane = t & 31;

    // stage B tile (vectorized): kp 0..63 x col 0..63, 16 uint4 per kp row
    {
        const uint4* srcH = (const uint4*)(g_Whi + c0);
        const uint4* srcL = (const uint4*)(g_Wlo + c0);
        for (int i = t; i < KP * 16; i += 256) {
            int kp = i >> 4, qc = i & 15;
            // global row pitch NCOLS/4 uint4; smem row pitch SPITCH u32
            uint4 vh = srcH[kp * (NCOLS / 4) + qc];
            uint4 vl = srcL[kp * (NCOLS / 4) + qc];
            *(uint4*)&sBhi[kp * SPITCH + qc * 4] = vh;
            *(uint4*)&sBlo[kp * SPITCH + qc * 4] = vl;
        }
    }
    __syncthreads();

    const int r0   = p0 + w * 32;
    const int qrow = lane >> 2;   // 0..7
    const int qk   = lane & 3;    // 0..3
    const int mg0  = r0 >> 4;     // fragment group of first 16-row tile

    float acc[2][8][4];
#pragma unroll
    for (int u = 0; u < 2; ++u)
#pragma unroll
        for (int s = 0; s < 8; ++s)
#pragma unroll
            for (int q = 0; q < 4; ++q) acc[u][s][q] = 0.0f;

    for (int ks = 0; ks < 8; ++ks) {
        const int kb = ks * 8;
        // coalesced A-fragment loads (512B contiguous per warp each)
        uint4 ah0 = g_fragHi[(mg0 * 8 + ks) * 32 + lane];
        uint4 al0 = g_fragLo[(mg0 * 8 + ks) * 32 + lane];
        uint4 ah1 = g_fragHi[((mg0 + 1) * 8 + ks) * 32 + lane];
        uint4 al1 = g_fragLo[((mg0 + 1) * 8 + ks) * 32 + lane];

        const uint32_t* rh0 = &sBhi[(kb + qk) * SPITCH + qrow];
        const uint32_t* rh1 = &sBhi[(kb + qk + 4) * SPITCH + qrow];
        const uint32_t* rl0 = &sBlo[(kb + qk) * SPITCH + qrow];
        const uint32_t* rl1 = &sBlo[(kb + qk + 4) * SPITCH + qrow];

#pragma unroll
        for (int s = 0; s < 8; ++s) {
            uint32_t bh0 = rh0[s * 8];
            uint32_t bh1 = rh1[s * 8];
            uint32_t bl0 = rl0[s * 8];
            uint32_t bl1 = rl1[s * 8];
            mma_bf16(acc[0][s], ah0, bh0, bh1);
            mma_bf16(acc[0][s], ah0, bl0, bl1);
            mma_bf16(acc[0][s], al0, bh0, bh1);
            mma_bf16(acc[1][s], ah1, bh0, bh1);
            mma_bf16(acc[1][s], ah1, bl0, bl1);
            mma_bf16(acc[1][s], al1, bh0, bh1);
        }
    }

    // epilogue: bias + direct coalesced float2 stores (two row tiles)
#pragma unroll
    for (int s = 0; s < 8; ++s) {
        int c = c0 + s * 8 + qk * 2;
        float b0 = bias[c], b1 = bias[c + 1];
#pragma unroll
        for (int u = 0; u < 2; ++u) {
            size_t r = (size_t)(r0 + 16 * u + qrow);
            float2 v0 = make_float2(acc[u][s][0] + b0, acc[u][s][1] + b1);
            float2 v1 = make_float2(acc[u][s][2] + b0, acc[u][s][3] + b1);
            *(float2*)&o[r * NCOLS + c]       = v0;
            *(float2*)&o[(r + 8) * NCOLS + c] = v1;
        }
    }
}

// ---------------------------------------------------------------------------
// Kernel 3: T[p] = 0.005 * eta[p] * sum_e Ey[p,e] * E0_slice[p,e]
// Table-driven gather (proven round 7).
// ---------------------------------------------------------------------------
__global__ void __launch_bounds__(256) esum_kernel(
    const float* ey_in, const float* E0r_in, const float* E0i_in,
    int stride, float* outT)
{
    const float* ey  = ey_in  ? ey_in  : g_Ey;
    const float* E0r = E0r_in ? E0r_in : g_zero;
    const float* E0i = E0i_in ? E0i_in : g_zero;

    const int p = blockIdx.x, t = threadIdx.x;
    const int f0  = p * 400;
    const int r0p = f0 / 960;
    const int c0p = f0 - r0p * 960;
    const int base = r0p * E0W + c0p;
    const int lim  = 960 - c0p;        // wrap when ab >= lim

    float sre = 0.f, sim = 0.f;
    const float* eyrow = ey + (size_t)p * NCOLS;

#pragma unroll 4
    for (int e = t; e < NCOLS; e += 256) {
        int tb  = g_tbl[e];
        int ab  = tb & 511;
        int idx = base + (tb >> 9) + ab + ((ab >= lim) ? 100 : 0);
        float g = eyrow[e];
        sre = fmaf(g, E0r[idx * stride], sre);
        sim = fmaf(g, E0i[idx * stride], sim);
    }

#pragma unroll
    for (int off = 16; off > 0; off >>= 1) {
        sre += __shfl_down_sync(0xffffffffu, sre, off);
        sim += __shfl_down_sync(0xffffffffu, sim, off);
    }
    __shared__ float wr[8], wi[8];
    if ((t & 31) == 0) { wr[t >> 5] = sre; wi[t >> 5] = sim; }
    __syncthreads();
    if (t == 0) {
        float tre = 0.f, tim = 0.f;
        for (int q = 0; q < 8; ++q) { tre += wr[q]; tim += wi[q]; }
        float s = 0.005f * g_eta[p];   // 2*C_EPSILON*dx*dx
        g_Tre[p] = s * tre;
        g_Tim[p] = s * tim;
        if (outT) outT[p] = s * tre;
    }
}

// ---------------------------------------------------------------------------
// Kernel 4 (fallback modes only): scalar-float pack, never exceeds cnt.
// ---------------------------------------------------------------------------
__global__ void pack_kernel(float* out, long long cnt, int mode)
{
    long long i = (long long)blockIdx.x * 256 + threadIdx.x;
    if (i >= cnt) return;
    float v = 0.f;
    if (mode == 1 || mode == 5) {
        if (i < EY_ELEMS) v = g_Ey[i];
        else {
            long long q = i - EY_ELEMS;
            if (q < 2 * NN) v = (q & 1) ? g_Tim[q >> 1] : g_Tre[q >> 1];
        }
    } else if (mode == 2) v = g_Ey[i];
    else if (mode == 3) v = (i & 1) ? g_Tim[i >> 1] : g_Tre[i >> 1];
    else if (mode == 4) v = g_Tre[i];
    out[i] = v;
}

// ---------------------------------------------------------------------------
extern "C" void kernel_launch(void* const* d_in, const int* in_sizes, int n_in,
                              void* d_out, int out_size)
{
    if (n_in > 64) n_in = 64;
    bool used[64];
    for (int i = 0; i < 64; ++i) used[i] = false;
    auto take = [&](int sz) -> const float* {
        for (int i = 0; i < n_in; ++i)
            if (!used[i] && in_sizes[i] == sz) {
                used[i] = true;
                return (const float*)d_in[i];
            }
        return nullptr;
    };

    const float* hs = take(2304);
    const float* E0r; const float* E0i; int e0stride;
    {
        const float* a = take(E0_ELEMS);
        if (a) { E0r = a; E0i = take(E0_ELEMS); e0stride = 1; }
        else {
            const float* c1 = take(2 * E0_ELEMS);
            const float* c2 = take(2 * E0_ELEMS);
            if (c1 && c2)      { E0r = c1; E0i = c2;     e0stride = 2; }
            else if (c1)       { E0r = c1; E0i = c1 + 1; e0stride = 2; }
            else               { E0r = nullptr; E0i = nullptr; e0stride = 1; }
        }
    }
    const float* nW0 = take(128);
    const float* nb0 = take(128);
    const float* nW1 = take(16384);
    const float* nb1 = take(128);
    const float* nW2 = take(128);
    const float* nb2 = take(1);
    const float* eW0 = take(128);
    const float* eb0 = take(128);
    const float* eW1 = take(16384);
    const float* eb1 = take(128);
    const float* eW2 = take(1843200);
    const float* eb2 = take(14400);
    float* out = (float*)d_out;

    const bool fast = (out_size == EY_ELEMS + NN);   // confirmed in round 4

    prep_kernel<<<(NCOLS + 255) / 256, 256>>>();
    mlp_kernel<<<NN, 128>>>(hs, nW0, nb0, nW1, nb1, nW2, nb2,
                            eW0, eb0, eW1, eb1);
    wpack_kernel<<<(KP * NCOLS + 255) / 256, 256>>>(eW2);
    hfrag_kernel<<<(2 * FRAG_N + 255) / 256, 256>>>();

    gemm_mma<<<dim3(NCOLS / GN, NN / GM), 256>>>(eb2, fast ? out : nullptr);

    esum_kernel<<<NN, 256>>>(fast ? out : nullptr, E0r, E0i, e0stride,
                             fast ? out + EY_ELEMS : nullptr);

    if (!fast) {
        long long cnt; int mode;
        if      (out_size == EY_ELEMS + 2 * NN) { mode = 1; cnt = out_size; }
        else if (out_size == EY_ELEMS)          { mode = 2; cnt = out_size; }
        else if (out_size == 2 * NN)            { mode = 3; cnt = out_size; }
        else if (out_size == NN)                { mode = 4; cnt = out_size; }
        else { mode = 5; cnt = out_size / 4; }
        if (cnt < 1) cnt = 1;
        pack_kernel<<<(unsigned)((cnt + 255) / 256), 256>>>(out, cnt, mode);
    }
}